// round 12
// baseline (speedup 1.0000x reference)
#include <cuda_runtime.h>
#include <cstdint>

#define DINLINE __device__ __forceinline__

// ---------------- geometry ----------------
#define NWARP 12
#define NTHR  384
#define WROWS 32
#define DTILE (NWARP * WROWS)   // 384 edges per tile
#define RING  3                 // cp.async ring slots per warp
#define CHUNK_B 4096            // 32 rows x 32 cols x 4B
#define NCHUNK 8                // chunks per tile (32 cols each)
#define PREF  2                 // chunks committed ahead

// ---------------- smem layout ----------------
#define OFF_W1F  0                       // 16ktf x 4np x 32 lanes x 16B = 32768
#define OFF_W2F  32768                   // 4ktf x 4np x 32 x 16B = 8192
#define OFF_CMB  40960                   // 12 warps x RING x CHUNK_B = 147456
#define OFF_B1   188416                  // 256B
#define OFF_B2   188672                  // 256B
#define OFF_FLAG 188928                  // 4B
#define SMEM_TOTAL 188992                // < 232448

// ---------------- helpers ----------------
DINLINE uint32_t s2u(const void* p) {
    uint32_t a;
    asm("{ .reg .u64 t; cvta.to.shared.u64 t, %1; cvt.u32.u64 %0, t; }" : "=r"(a) : "l"(p));
    return a;
}

// pack two fp32 -> f16x2 (lo = first arg, hi = second)
DINLINE uint32_t f2h2(float lo, float hi) {
    uint32_t r;
    asm("cvt.rn.f16x2.f32 %0, %1, %2;" : "=r"(r) : "f"(hi), "f"(lo));
    return r;
}

DINLINE void cp16(uint32_t dst, const void* src) {
    asm volatile("cp.async.cg.shared.global [%0], [%1], 16;" :: "r"(dst), "l"(src));
}
DINLINE void cp_commit() { asm volatile("cp.async.commit_group;" ::: "memory"); }
template <int N> DINLINE void cp_wait() {
    asm volatile("cp.async.wait_group %0;" :: "n"(N) : "memory");
}

// D += A(m16k16,row,f16) * B(k16n8,col,f16), fp32 accumulate
DINLINE void mmaf16(float* c, uint32_t a0, uint32_t a1, uint32_t a2, uint32_t a3,
                    uint32_t b0, uint32_t b1) {
    asm volatile(
        "mma.sync.aligned.m16n8k16.row.col.f32.f16.f16.f32 "
        "{%0,%1,%2,%3}, {%4,%5,%6,%7}, {%8,%9}, {%0,%1,%2,%3};"
        : "+f"(c[0]), "+f"(c[1]), "+f"(c[2]), "+f"(c[3])
        : "r"(a0), "r"(a1), "r"(a2), "r"(a3), "r"(b0), "r"(b1));
}

// ---------------- per-warp chunk issue (fp32 comb) ----------------
// chunk c of a tile: 32 warp-rows x 32 cols [c*32, c*32+32).
// c>>1 selects tensor (src|dest|ea|u), (c&1)*32 the col offset within it.
// smem: row stride 128B, float4 quad q stored at q ^ (row&7).
DINLINE void issue_chunk(uint32_t slot, long ebase, int E, int c, int lane,
                         const float* __restrict__ s0, const float* __restrict__ s1,
                         const float* __restrict__ s2, const float* __restrict__ u,
                         const void* __restrict__ bat, int is64) {
    const int tensor = c >> 1;
    const int coloff = (c & 1) * 32;
#pragma unroll
    for (int i = 0; i < 8; i++) {
        int flat = i * 32 + lane;
        int row = flat >> 3, q = flat & 7;
        long e = ebase + row; if (e >= E) e = E - 1;
        const float* p;
        if (tensor == 0)      p = s0 + e * 64 + coloff + q * 4;
        else if (tensor == 1) p = s1 + e * 64 + coloff + q * 4;
        else if (tensor == 2) p = s2 + e * 64 + coloff + q * 4;
        else {
            long b = is64 ? (long)((const long long*)bat)[e]
                          : (long)((const int*)bat)[e];
            p = u + b * 64 + coloff + q * 4;
        }
        cp16(slot + (uint32_t)(row * 128) + (uint32_t)((q ^ (row & 7)) << 4), p);
    }
}

// ---------------- kernel ----------------
__global__ void __launch_bounds__(NTHR, 1)
megnet_edge_kernel(const float* __restrict__ src, const float* __restrict__ dst,
                   const float* __restrict__ ea,  const float* __restrict__ u,
                   const int* __restrict__ bat,
                   const float* __restrict__ W1, const float* __restrict__ b1,
                   const float* __restrict__ W2, const float* __restrict__ b2,
                   float* __restrict__ out, int E, int NT) {
    extern __shared__ char smem[];
    const uint32_t sb = s2u(smem);
    const int tid = threadIdx.x;
    const int w = tid >> 5;
    const int lane = tid & 31;

    // ---- one-time: pack W1/W2 into fp16 m16n8k16 B-fragments ----
    // slot s: lane = s&31, np = (s>>5)&3, ktf = s>>7
    // uint4 = {b0(nt=2np), b1(nt=2np), b0(nt=2np+1), b1(nt=2np+1)}
    for (int s = tid; s < 2048; s += NTHR) {
        int l = s & 31, np = (s >> 5) & 3, ktf = s >> 7;
        int g = l >> 2, t = l & 3;
        int kb = ktf * 16 + 2 * t;
        int n0 = (2 * np) * 8 + g, n1 = n0 + 8;
        uint4 v;
        v.x = f2h2(W1[kb * 64 + n0],       W1[(kb + 1) * 64 + n0]);
        v.y = f2h2(W1[(kb + 8) * 64 + n0], W1[(kb + 9) * 64 + n0]);
        v.z = f2h2(W1[kb * 64 + n1],       W1[(kb + 1) * 64 + n1]);
        v.w = f2h2(W1[(kb + 8) * 64 + n1], W1[(kb + 9) * 64 + n1]);
        *(uint4*)(smem + OFF_W1F + (size_t)s * 16) = v;
    }
    for (int s = tid; s < 512; s += NTHR) {
        int l = s & 31, np = (s >> 5) & 3, ktf = s >> 7;
        int g = l >> 2, t = l & 3;
        int kb = ktf * 16 + 2 * t;
        int n0 = (2 * np) * 8 + g, n1 = n0 + 8;
        uint4 v;
        v.x = f2h2(W2[kb * 64 + n0],       W2[(kb + 1) * 64 + n0]);
        v.y = f2h2(W2[(kb + 8) * 64 + n0], W2[(kb + 9) * 64 + n0]);
        v.z = f2h2(W2[kb * 64 + n1],       W2[(kb + 1) * 64 + n1]);
        v.w = f2h2(W2[(kb + 8) * 64 + n1], W2[(kb + 9) * 64 + n1]);
        *(uint4*)(smem + OFF_W2F + (size_t)s * 16) = v;
    }
    if (tid < 64) {
        ((float*)(smem + OFF_B1))[tid] = b1[tid];
        ((float*)(smem + OFF_B2))[tid] = b2[tid];
    }
    if (tid == 0) {
        // batch dtype sniff: int64 payload (values < 2^31) has all-zero odd words
        int is64 = 1;
        for (int i = 1; i < 32; i += 2)
            if (bat[i] != 0) { is64 = 0; break; }
        *(int*)(smem + OFF_FLAG) = is64;
    }
    __syncthreads();
    const int is64 = *(const int*)(smem + OFF_FLAG);
    const float* b1s = (const float*)(smem + OFF_B1);
    const float* b2s = (const float*)(smem + OFF_B2);

    // ---- per-warp constants ----
    const int g = lane >> 2;                     // fragment row 0..7
    const int t = lane & 3;
    const uint32_t ringbase = sb + OFF_CMB + (uint32_t)w * (RING * CHUNK_B);

    const int bid = blockIdx.x, grid = gridDim.x;
    const int numT = (NT - bid + grid - 1) / grid;
    const long total = (long)numT * NCHUNK;

    float C[64];                                 // [m(2)][nt(8)][4]

    // prologue: PREF chunks ahead
#pragma unroll
    for (int pc = 0; pc < PREF; pc++) {
        if (pc < total) {
            issue_chunk(ringbase + (uint32_t)(pc % RING) * CHUNK_B,
                        (long)bid * DTILE + w * WROWS, E, pc, lane,
                        src, dst, ea, u, bat, is64);
        }
        cp_commit();   // commit even if empty to keep group count in sync
    }

    for (long n = 0; n < total; n++) {
        const int c = (int)(n & (NCHUNK - 1));
        const long tile = bid + (n >> 3) * grid;

        if (n + PREF < total) {
            long np_ = n + PREF;
            issue_chunk(ringbase + (uint32_t)(np_ % RING) * CHUNK_B,
                        (bid + (np_ >> 3) * grid) * DTILE + w * WROWS, E,
                        (int)(np_ & (NCHUNK - 1)), lane,
                        src, dst, ea, u, bat, is64);
            cp_commit();
        }
        cp_wait<PREF>();          // chunk n landed (PREF groups may remain)
        __syncwarp();

        if (c == 0) {
#pragma unroll
            for (int i = 0; i < 64; i++) C[i] = 0.f;
        }

        // ---------- layer-1 partial: 2 k16-groups of this chunk ----------
        const char* sbase = smem + OFF_CMB + (size_t)w * (RING * CHUNK_B)
                                 + (size_t)(n % RING) * CHUNK_B;
#pragma unroll
        for (int kl = 0; kl < 2; kl++) {
            const int ktf = c * 2 + kl;
            // A fragments: fp32 pairs from smem -> f16x2
            const uint32_t q0 = (uint32_t)(4 * kl + (t >> 1));
            const uint32_t off0 = (((q0 ^ (uint32_t)g) << 4) + (uint32_t)((t & 1) * 8));
            const uint32_t off2 = ((((q0 + 2) ^ (uint32_t)g) << 4) + (uint32_t)((t & 1) * 8));
            uint32_t a[2][4];
#pragma unroll
            for (int m = 0; m < 2; m++) {
                const char* rb = sbase + (m * 16 + g) * 128;
                float2 v;
                v = *(const float2*)(rb + off0);        a[m][0] = f2h2(v.x, v.y);
                v = *(const float2*)(rb + 1024 + off0); a[m][1] = f2h2(v.x, v.y);
                v = *(const float2*)(rb + off2);        a[m][2] = f2h2(v.x, v.y);
                v = *(const float2*)(rb + 1024 + off2); a[m][3] = f2h2(v.x, v.y);
            }
            const char* wf = smem + OFF_W1F + (size_t)ktf * 2048 + (size_t)lane * 16;
#pragma unroll
            for (int np = 0; np < 4; np++) {
                uint4 bv = *(const uint4*)(wf + np * 512);
#pragma unroll
                for (int m = 0; m < 2; m++) {
                    float* Cp = C + m * 32 + np * 8;
                    mmaf16(Cp,     a[m][0], a[m][1], a[m][2], a[m][3], bv.x, bv.y);
                    mmaf16(Cp + 4, a[m][0], a[m][1], a[m][2], a[m][3], bv.z, bv.w);
                }
            }
        }

        if (c != NCHUNK - 1) continue;

        // ---------- tail: per m-sub, h = relu(C+b1) -> f16 A regs (no smem) ----------
        const long e0 = tile * DTILE + w * WROWS + g;
#pragma unroll
        for (int m = 0; m < 2; m++) {
            // C-fragment (c0,c1,c2,c3) == fp16 A-fragment pair layout: direct cvt
            uint32_t ah[16];
#pragma unroll
            for (int nt = 0; nt < 8; nt++) {
                float2 bb = *(const float2*)(b1s + nt * 8 + 2 * t);
                const float* Cm = C + m * 32 + nt * 4;
                ah[nt * 2]     = f2h2(fmaxf(Cm[0] + bb.x, 0.f), fmaxf(Cm[1] + bb.y, 0.f));
                ah[nt * 2 + 1] = f2h2(fmaxf(Cm[2] + bb.x, 0.f), fmaxf(Cm[3] + bb.y, 0.f));
            }

            const long e = e0 + m * 16;
            // layer 2 in n-halves to cap register pressure at C2[16]
#pragma unroll
            for (int nh = 0; nh < 2; nh++) {
                float C2[16];
#pragma unroll
                for (int i = 0; i < 16; i++) C2[i] = 0.f;
#pragma unroll
                for (int ktf = 0; ktf < 4; ktf++) {
                    const char* wf = smem + OFF_W2F + (size_t)ktf * 2048
                                         + (size_t)(nh * 2) * 512 + (size_t)lane * 16;
#pragma unroll
                    for (int npl = 0; npl < 2; npl++) {
                        uint4 bv = *(const uint4*)(wf + npl * 512);
                        mmaf16(C2 + npl * 8,
                               ah[4 * ktf], ah[4 * ktf + 1], ah[4 * ktf + 2], ah[4 * ktf + 3],
                               bv.x, bv.y);
                        mmaf16(C2 + npl * 8 + 4,
                               ah[4 * ktf], ah[4 * ktf + 1], ah[4 * ktf + 2], ah[4 * ktf + 3],
                               bv.z, bv.w);
                    }
                }

                // out = relu(C2 + b2) -> gmem  (local j -> global nt = 4*nh + j)
#pragma unroll
                for (int j = 0; j < 4; j++) {
                    const int col0 = (4 * nh + j) * 8 + 2 * t;
                    float2 bb = *(const float2*)(b2s + col0);
                    const float* Cm = C2 + j * 4;
                    if (e < E) {
                        float2 v = make_float2(fmaxf(Cm[0] + bb.x, 0.f),
                                               fmaxf(Cm[1] + bb.y, 0.f));
                        *(float2*)(out + e * 64 + col0) = v;
                    }
                    if (e + 8 < E) {
                        float2 v = make_float2(fmaxf(Cm[2] + bb.x, 0.f),
                                               fmaxf(Cm[3] + bb.y, 0.f));
                        *(float2*)(out + (e + 8) * 64 + col0) = v;
                    }
                }
            }
        }
    }
}

// ---------------- launch ----------------
extern "C" void kernel_launch(void* const* d_in, const int* in_sizes, int n_in,
                              void* d_out, int out_size) {
    const float* src = (const float*)d_in[0];
    const float* dst = (const float*)d_in[1];
    const float* ea  = (const float*)d_in[2];
    const float* u   = (const float*)d_in[3];
    const int*   bat = (const int*)d_in[4];   // int32 or int64 payload; sniffed in-kernel
    const float* W1  = (const float*)d_in[5];
    const float* b1  = (const float*)d_in[6];
    const float* W2  = (const float*)d_in[7];
    const float* b2  = (const float*)d_in[8];
    float* out = (float*)d_out;

    int E  = in_sizes[0] / 64;
    int NT = (E + DTILE - 1) / DTILE;

    int dev = 0;
    cudaGetDevice(&dev);
    int nsm = 148;
    cudaDeviceGetAttribute(&nsm, cudaDevAttrMultiProcessorCount, dev);
    int grid = (NT < nsm) ? NT : nsm;

    cudaFuncSetAttribute(megnet_edge_kernel,
                         cudaFuncAttributeMaxDynamicSharedMemorySize, SMEM_TOTAL);
    megnet_edge_kernel<<<grid, NTHR, SMEM_TOTAL>>>(src, dst, ea, u, bat,
                                                   W1, b1, W2, b2, out, E, NT);
    (void)n_in; (void)out_size;
}

// round 14
// speedup vs baseline: 2.0294x; 2.0294x over previous
#include <cuda_runtime.h>
#include <cstdint>

#define DINLINE __device__ __forceinline__

// ---------------- geometry ----------------
#define NWARP 8
#define NTHR  256
#define WROWS 32
#define DTILE (NWARP * WROWS)   // 256 edges per tile
#define RING  5                 // cp.async ring slots per warp
#define CHUNK_B 4096            // 32 rows x 32 cols x 4B
#define NCHUNK 8                // chunks per tile (32 cols each)
#define PREF  4                 // chunks committed ahead

// ---------------- smem layout ----------------
#define OFF_W1F  0                       // 16ktf x 4np x 32 lanes x 16B = 32768
#define OFF_W2F  32768                   // 4ktf x 4np x 32 x 16B = 8192
#define OFF_CMB  40960                   // 8 warps x RING x CHUNK_B = 163840
#define OFF_B1   204800                  // 256B
#define OFF_B2   205056                  // 256B
#define OFF_FLAG 205312                  // 4B
#define SMEM_TOTAL 205376                // < 232448

// ---------------- helpers ----------------
DINLINE uint32_t s2u(const void* p) {
    uint32_t a;
    asm("{ .reg .u64 t; cvta.to.shared.u64 t, %1; cvt.u32.u64 %0, t; }" : "=r"(a) : "l"(p));
    return a;
}

// pack two fp32 -> f16x2 (lo = first arg, hi = second)
DINLINE uint32_t f2h2(float lo, float hi) {
    uint32_t r;
    asm("cvt.rn.f16x2.f32 %0, %1, %2;" : "=r"(r) : "f"(hi), "f"(lo));
    return r;
}

DINLINE void cp16(uint32_t dst, const void* src) {
    asm volatile("cp.async.cg.shared.global [%0], [%1], 16;" :: "r"(dst), "l"(src));
}
DINLINE void cp_commit() { asm volatile("cp.async.commit_group;" ::: "memory"); }
template <int N> DINLINE void cp_wait() {
    asm volatile("cp.async.wait_group %0;" :: "n"(N) : "memory");
}

// D += A(m16k16,row,f16) * B(k16n8,col,f16), fp32 accumulate
DINLINE void mmaf16(float* c, uint32_t a0, uint32_t a1, uint32_t a2, uint32_t a3,
                    uint32_t b0, uint32_t b1) {
    asm volatile(
        "mma.sync.aligned.m16n8k16.row.col.f32.f16.f16.f32 "
        "{%0,%1,%2,%3}, {%4,%5,%6,%7}, {%8,%9}, {%0,%1,%2,%3};"
        : "+f"(c[0]), "+f"(c[1]), "+f"(c[2]), "+f"(c[3])
        : "r"(a0), "r"(a1), "r"(a2), "r"(a3), "r"(b0), "r"(b1));
}

// ---------------- per-warp chunk issue (fp32 comb) ----------------
// chunk c of a tile: 32 warp-rows x 32 cols [c*32, c*32+32).
// c>>1 selects tensor (src|dest|ea|u), (c&1)*32 the col offset within it.
// u-gather uses pre-loaded per-lane batch index bt (lane r holds bat[ebase+r]),
// distributed via shfl -> no dependent LDG on the issue path.
// smem: row stride 128B, float4 quad q stored at q ^ (row&7).
DINLINE void issue_chunk(uint32_t slot, long ebase, int E, int c, int lane, int bt,
                         const float* __restrict__ s0, const float* __restrict__ s1,
                         const float* __restrict__ s2, const float* __restrict__ u) {
    const int tensor = c >> 1;
    const int coloff = (c & 1) * 32;
#pragma unroll
    for (int i = 0; i < 8; i++) {
        int flat = i * 32 + lane;
        int row = flat >> 3, q = flat & 7;
        long e = ebase + row; if (e >= E) e = E - 1;
        const float* p;
        if (tensor == 0)      p = s0 + e * 64 + coloff + q * 4;
        else if (tensor == 1) p = s1 + e * 64 + coloff + q * 4;
        else if (tensor == 2) p = s2 + e * 64 + coloff + q * 4;
        else {
            int b = __shfl_sync(0xffffffffu, bt, row);
            p = u + (long)b * 64 + coloff + q * 4;
        }
        cp16(slot + (uint32_t)(row * 128) + (uint32_t)((q ^ (row & 7)) << 4), p);
    }
}

// per-lane batch prefetch for one tile: lane r -> bat[ebase + r] (clamped)
DINLINE int load_bt(long ebase, int E, int lane, const void* __restrict__ bat, int is64) {
    long e = ebase + lane; if (e >= E) e = E - 1;
    return is64 ? (int)((const long long*)bat)[e] : ((const int*)bat)[e];
}

// ---------------- kernel ----------------
__global__ void __launch_bounds__(NTHR, 1)
megnet_edge_kernel(const float* __restrict__ src, const float* __restrict__ dst,
                   const float* __restrict__ ea,  const float* __restrict__ u,
                   const int* __restrict__ bat,
                   const float* __restrict__ W1, const float* __restrict__ b1,
                   const float* __restrict__ W2, const float* __restrict__ b2,
                   float* __restrict__ out, int E, int NT) {
    extern __shared__ char smem[];
    const uint32_t sb = s2u(smem);
    const int tid = threadIdx.x;
    const int w = tid >> 5;
    const int lane = tid & 31;

    // ---- one-time: pack W1/W2 into fp16 m16n8k16 B-fragments ----
    // slot s: lane = s&31, np = (s>>5)&3, ktf = s>>7
    // uint4 = {b0(nt=2np), b1(nt=2np), b0(nt=2np+1), b1(nt=2np+1)}
    for (int s = tid; s < 2048; s += NTHR) {
        int l = s & 31, np = (s >> 5) & 3, ktf = s >> 7;
        int g = l >> 2, t = l & 3;
        int kb = ktf * 16 + 2 * t;
        int n0 = (2 * np) * 8 + g, n1 = n0 + 8;
        uint4 v;
        v.x = f2h2(W1[kb * 64 + n0],       W1[(kb + 1) * 64 + n0]);
        v.y = f2h2(W1[(kb + 8) * 64 + n0], W1[(kb + 9) * 64 + n0]);
        v.z = f2h2(W1[kb * 64 + n1],       W1[(kb + 1) * 64 + n1]);
        v.w = f2h2(W1[(kb + 8) * 64 + n1], W1[(kb + 9) * 64 + n1]);
        *(uint4*)(smem + OFF_W1F + (size_t)s * 16) = v;
    }
    for (int s = tid; s < 512; s += NTHR) {
        int l = s & 31, np = (s >> 5) & 3, ktf = s >> 7;
        int g = l >> 2, t = l & 3;
        int kb = ktf * 16 + 2 * t;
        int n0 = (2 * np) * 8 + g, n1 = n0 + 8;
        uint4 v;
        v.x = f2h2(W2[kb * 64 + n0],       W2[(kb + 1) * 64 + n0]);
        v.y = f2h2(W2[(kb + 8) * 64 + n0], W2[(kb + 9) * 64 + n0]);
        v.z = f2h2(W2[kb * 64 + n1],       W2[(kb + 1) * 64 + n1]);
        v.w = f2h2(W2[(kb + 8) * 64 + n1], W2[(kb + 9) * 64 + n1]);
        *(uint4*)(smem + OFF_W2F + (size_t)s * 16) = v;
    }
    if (tid < 64) {
        ((float*)(smem + OFF_B1))[tid] = b1[tid];
        ((float*)(smem + OFF_B2))[tid] = b2[tid];
    }
    if (tid == 0) {
        // batch dtype sniff: int64 payload (values < 2^31) has all-zero odd words
        int is64 = 1;
        for (int i = 1; i < 32; i += 2)
            if (bat[i] != 0) { is64 = 0; break; }
        *(int*)(smem + OFF_FLAG) = is64;
    }
    __syncthreads();
    const int is64 = *(const int*)(smem + OFF_FLAG);
    const float* b1s = (const float*)(smem + OFF_B1);
    const float* b2s = (const float*)(smem + OFF_B2);

    // ---- per-warp constants ----
    const int g = lane >> 2;                     // fragment row 0..7
    const int t = lane & 3;
    const uint32_t ringbase = sb + OFF_CMB + (uint32_t)w * (RING * CHUNK_B);

    const int bid = blockIdx.x, grid = gridDim.x;
    const int numT = (NT - bid + grid - 1) / grid;
    const long total = (long)numT * NCHUNK;

    float C[64];                                 // [m(2)][nt(8)][4]

    // batch indices for the first tile (consumed by its u-chunks c=6,7)
    int bt = load_bt((long)bid * DTILE + w * WROWS, E, lane, bat, is64);

    // prologue: PREF chunks ahead (c=0..3, no u-chunks -> bt not needed yet)
#pragma unroll
    for (int pc = 0; pc < PREF; pc++) {
        if (pc < total) {
            issue_chunk(ringbase + (uint32_t)pc * CHUNK_B,
                        (long)bid * DTILE + w * WROWS, E, pc, lane, bt,
                        src, dst, ea, u);
        }
        cp_commit();   // commit even if empty to keep group count in sync
    }

    int slot_cons = 0;            // ring slot of chunk n
    int slot_iss  = PREF;         // ring slot of chunk n+PREF (PREF < RING)

    for (long n = 0; n < total; n++) {
        const int c = (int)(n & (NCHUNK - 1));
        const long tile = bid + (n >> 3) * grid;

        if (n + PREF < total) {
            long np_ = n + PREF;
            int cc = (int)(np_ & (NCHUNK - 1));
            long tl = bid + (np_ >> 3) * grid;
            if (cc == 0)          // new tile enters the pipeline: refresh bt early
                bt = load_bt(tl * DTILE + w * WROWS, E, lane, bat, is64);
            issue_chunk(ringbase + (uint32_t)slot_iss * CHUNK_B,
                        tl * DTILE + w * WROWS, E, cc, lane, bt,
                        src, dst, ea, u);
            cp_commit();
        }
        if (++slot_iss == RING) slot_iss = 0;
        cp_wait<PREF>();          // chunk n landed (PREF groups may remain)
        __syncwarp();

        if (c == 0) {
#pragma unroll
            for (int i = 0; i < 64; i++) C[i] = 0.f;
        }

        // ---------- layer-1 partial: 2 k16-groups of this chunk ----------
        const char* sbase = smem + OFF_CMB + (size_t)w * (RING * CHUNK_B)
                                 + (size_t)slot_cons * CHUNK_B;
        if (++slot_cons == RING) slot_cons = 0;
#pragma unroll
        for (int kl = 0; kl < 2; kl++) {
            const int ktf = c * 2 + kl;
            // A fragments: fp32 pairs from smem -> f16x2
            const uint32_t q0 = (uint32_t)(4 * kl + (t >> 1));
            const uint32_t off0 = (((q0 ^ (uint32_t)g) << 4) + (uint32_t)((t & 1) * 8));
            const uint32_t off2 = ((((q0 + 2) ^ (uint32_t)g) << 4) + (uint32_t)((t & 1) * 8));
            uint32_t a[2][4];
#pragma unroll
            for (int m = 0; m < 2; m++) {
                const char* rb = sbase + (m * 16 + g) * 128;
                float2 v;
                v = *(const float2*)(rb + off0);        a[m][0] = f2h2(v.x, v.y);
                v = *(const float2*)(rb + 1024 + off0); a[m][1] = f2h2(v.x, v.y);
                v = *(const float2*)(rb + off2);        a[m][2] = f2h2(v.x, v.y);
                v = *(const float2*)(rb + 1024 + off2); a[m][3] = f2h2(v.x, v.y);
            }
            const char* wf = smem + OFF_W1F + (size_t)ktf * 2048 + (size_t)lane * 16;
#pragma unroll
            for (int np = 0; np < 4; np++) {
                uint4 bv = *(const uint4*)(wf + np * 512);
#pragma unroll
                for (int m = 0; m < 2; m++) {
                    float* Cp = C + m * 32 + np * 8;
                    mmaf16(Cp,     a[m][0], a[m][1], a[m][2], a[m][3], bv.x, bv.y);
                    mmaf16(Cp + 4, a[m][0], a[m][1], a[m][2], a[m][3], bv.z, bv.w);
                }
            }
        }

        if (c != NCHUNK - 1) continue;

        // ---------- tail: per m-sub, h = relu(C+b1) -> f16 A regs (no smem) ----------
        const long e0 = tile * DTILE + w * WROWS + g;
#pragma unroll
        for (int m = 0; m < 2; m++) {
            // C-fragment (c0,c1,c2,c3) == fp16 A-fragment pair layout: direct cvt
            uint32_t ah[16];
#pragma unroll
            for (int nt = 0; nt < 8; nt++) {
                float2 bb = *(const float2*)(b1s + nt * 8 + 2 * t);
                const float* Cm = C + m * 32 + nt * 4;
                ah[nt * 2]     = f2h2(fmaxf(Cm[0] + bb.x, 0.f), fmaxf(Cm[1] + bb.y, 0.f));
                ah[nt * 2 + 1] = f2h2(fmaxf(Cm[2] + bb.x, 0.f), fmaxf(Cm[3] + bb.y, 0.f));
            }

            // layer 2: C2[32] = h[16,64] @ W2  (A regs = ah quads)
            float C2[32];
#pragma unroll
            for (int i = 0; i < 32; i++) C2[i] = 0.f;
#pragma unroll
            for (int ktf = 0; ktf < 4; ktf++) {
                const char* wf = smem + OFF_W2F + (size_t)ktf * 2048 + (size_t)lane * 16;
#pragma unroll
                for (int np = 0; np < 4; np++) {
                    uint4 bv = *(const uint4*)(wf + np * 512);
                    mmaf16(C2 + np * 8,
                           ah[4 * ktf], ah[4 * ktf + 1], ah[4 * ktf + 2], ah[4 * ktf + 3],
                           bv.x, bv.y);
                    mmaf16(C2 + np * 8 + 4,
                           ah[4 * ktf], ah[4 * ktf + 1], ah[4 * ktf + 2], ah[4 * ktf + 3],
                           bv.z, bv.w);
                }
            }

            // out = relu(C2 + b2) -> gmem
            const long e = e0 + m * 16;
#pragma unroll
            for (int nt = 0; nt < 8; nt++) {
                const int col0 = nt * 8 + 2 * t;
                float2 bb = *(const float2*)(b2s + col0);
                const float* Cm = C2 + nt * 4;
                if (e < E) {
                    float2 v = make_float2(fmaxf(Cm[0] + bb.x, 0.f),
                                           fmaxf(Cm[1] + bb.y, 0.f));
                    *(float2*)(out + e * 64 + col0) = v;
                }
                if (e + 8 < E) {
                    float2 v = make_float2(fmaxf(Cm[2] + bb.x, 0.f),
                                           fmaxf(Cm[3] + bb.y, 0.f));
                    *(float2*)(out + (e + 8) * 64 + col0) = v;
                }
            }
        }
    }
}

// ---------------- launch ----------------
extern "C" void kernel_launch(void* const* d_in, const int* in_sizes, int n_in,
                              void* d_out, int out_size) {
    const float* src = (const float*)d_in[0];
    const float* dst = (const float*)d_in[1];
    const float* ea  = (const float*)d_in[2];
    const float* u   = (const float*)d_in[3];
    const int*   bat = (const int*)d_in[4];   // int32 or int64 payload; sniffed in-kernel
    const float* W1  = (const float*)d_in[5];
    const float* b1  = (const float*)d_in[6];
    const float* W2  = (const float*)d_in[7];
    const float* b2  = (const float*)d_in[8];
    float* out = (float*)d_out;

    int E  = in_sizes[0] / 64;
    int NT = (E + DTILE - 1) / DTILE;

    int dev = 0;
    cudaGetDevice(&dev);
    int nsm = 148;
    cudaDeviceGetAttribute(&nsm, cudaDevAttrMultiProcessorCount, dev);
    int grid = (NT < nsm) ? NT : nsm;

    cudaFuncSetAttribute(megnet_edge_kernel,
                         cudaFuncAttributeMaxDynamicSharedMemorySize, SMEM_TOTAL);
    megnet_edge_kernel<<<grid, NTHR, SMEM_TOTAL>>>(src, dst, ea, u, bat,
                                                   W1, b1, W2, b2, out, E, NT);
    (void)n_in; (void)out_size;
}

// round 17
// speedup vs baseline: 2.0958x; 1.0327x over previous
#include <cuda_runtime.h>
#include <cstdint>

#define DINLINE __device__ __forceinline__

// ---------------- geometry ----------------
#define NWARP 8
#define NTHR  256
#define WROWS 32
#define DTILE (NWARP * WROWS)   // 256 edges per tile
#define RING  5                 // cp.async ring slots per warp
#define CHUNK_B 4096            // 32 rows x 32 cols x 4B
#define NCHUNK 8                // chunks per tile (32 cols each)
#define PREF  4                 // chunks committed ahead

// ---------------- smem layout ----------------
#define OFF_W1F  0                       // 16ktf x 4np x 32 lanes x 16B = 32768
#define OFF_W2F  32768                   // 4ktf x 4np x 32 x 16B = 8192
#define OFF_CMB  40960                   // 8 warps x RING x CHUNK_B = 163840
#define OFF_B1   204800                  // 256B
#define OFF_B2   205056                  // 256B
#define OFF_FLAG 205312                  // 4B
#define OFF_OB   205440                  // 8 warps x 2KB output bounce = 16384
#define SMEM_TOTAL 221824                // < 232448

// ---------------- helpers ----------------
DINLINE uint32_t s2u(const void* p) {
    uint32_t a;
    asm("{ .reg .u64 t; cvta.to.shared.u64 t, %1; cvt.u32.u64 %0, t; }" : "=r"(a) : "l"(p));
    return a;
}

// pack two fp32 -> f16x2 (lo = first arg, hi = second)
DINLINE uint32_t f2h2(float lo, float hi) {
    uint32_t r;
    asm("cvt.rn.f16x2.f32 %0, %1, %2;" : "=r"(r) : "f"(hi), "f"(lo));
    return r;
}

DINLINE void cp16(uint32_t dst, const void* src) {
    asm volatile("cp.async.cg.shared.global [%0], [%1], 16;" :: "r"(dst), "l"(src));
}
DINLINE void cp_commit() { asm volatile("cp.async.commit_group;" ::: "memory"); }
template <int N> DINLINE void cp_wait() {
    asm volatile("cp.async.wait_group %0;" :: "n"(N) : "memory");
}

// D += A(m16k16,row,f16) * B(k16n8,col,f16), fp32 accumulate
DINLINE void mmaf16(float* c, uint32_t a0, uint32_t a1, uint32_t a2, uint32_t a3,
                    uint32_t b0, uint32_t b1) {
    asm volatile(
        "mma.sync.aligned.m16n8k16.row.col.f32.f16.f16.f32 "
        "{%0,%1,%2,%3}, {%4,%5,%6,%7}, {%8,%9}, {%0,%1,%2,%3};"
        : "+f"(c[0]), "+f"(c[1]), "+f"(c[2]), "+f"(c[3])
        : "r"(a0), "r"(a1), "r"(a2), "r"(a3), "r"(b0), "r"(b1));
}

// ---------------- per-warp chunk issue (fp32 comb) ----------------
// chunk c of a tile: 32 warp-rows x 32 cols [c*32, c*32+32).
// c>>1 selects tensor (src|dest|ea|u), (c&1)*32 the col offset within it.
// u-gather uses pre-loaded per-lane batch index bt (lane r holds bat[ebase+r]),
// distributed via shfl -> no dependent LDG on the issue path.
// smem: row stride 128B, float4 quad q stored at q ^ (row&7).
DINLINE void issue_chunk(uint32_t slot, int ebase, int E, int c, int lane, int bt,
                         const float* __restrict__ s0, const float* __restrict__ s1,
                         const float* __restrict__ s2, const float* __restrict__ u) {
    const int tensor = c >> 1;
    const int coloff = (c & 1) * 32;
#pragma unroll
    for (int i = 0; i < 8; i++) {
        int flat = i * 32 + lane;
        int row = flat >> 3, q = flat & 7;
        int e = ebase + row; if (e >= E) e = E - 1;
        const float* p;
        if (tensor == 0)      p = s0 + (size_t)e * 64 + coloff + q * 4;
        else if (tensor == 1) p = s1 + (size_t)e * 64 + coloff + q * 4;
        else if (tensor == 2) p = s2 + (size_t)e * 64 + coloff + q * 4;
        else {
            int b = __shfl_sync(0xffffffffu, bt, row);
            p = u + (size_t)b * 64 + coloff + q * 4;
        }
        cp16(slot + (uint32_t)(row * 128) + (uint32_t)((q ^ (row & 7)) << 4), p);
    }
}

// per-lane batch prefetch for one tile: lane r -> bat[ebase + r] (clamped)
DINLINE int load_bt(int ebase, int E, int lane, const void* __restrict__ bat, int is64) {
    int e = ebase + lane; if (e >= E) e = E - 1;
    return is64 ? (int)((const long long*)bat)[e] : ((const int*)bat)[e];
}

// ---------------- kernel ----------------
__global__ void __launch_bounds__(NTHR, 1)
megnet_edge_kernel(const float* __restrict__ src, const float* __restrict__ dst,
                   const float* __restrict__ ea,  const float* __restrict__ u,
                   const int* __restrict__ bat,
                   const float* __restrict__ W1, const float* __restrict__ b1,
                   const float* __restrict__ W2, const float* __restrict__ b2,
                   float* __restrict__ out, int E, int NT) {
    extern __shared__ char smem[];
    const uint32_t sb = s2u(smem);
    const int tid = threadIdx.x;
    const int w = tid >> 5;
    const int lane = tid & 31;

    // ---- one-time: pack W1/W2 into fp16 m16n8k16 B-fragments ----
    // slot s: lane = s&31, np = (s>>5)&3, ktf = s>>7
    // uint4 = {b0(nt=2np), b1(nt=2np), b0(nt=2np+1), b1(nt=2np+1)}
    for (int s = tid; s < 2048; s += NTHR) {
        int l = s & 31, np = (s >> 5) & 3, ktf = s >> 7;
        int g = l >> 2, t = l & 3;
        int kb = ktf * 16 + 2 * t;
        int n0 = (2 * np) * 8 + g, n1 = n0 + 8;
        uint4 v;
        v.x = f2h2(W1[kb * 64 + n0],       W1[(kb + 1) * 64 + n0]);
        v.y = f2h2(W1[(kb + 8) * 64 + n0], W1[(kb + 9) * 64 + n0]);
        v.z = f2h2(W1[kb * 64 + n1],       W1[(kb + 1) * 64 + n1]);
        v.w = f2h2(W1[(kb + 8) * 64 + n1], W1[(kb + 9) * 64 + n1]);
        *(uint4*)(smem + OFF_W1F + (size_t)s * 16) = v;
    }
    for (int s = tid; s < 512; s += NTHR) {
        int l = s & 31, np = (s >> 5) & 3, ktf = s >> 7;
        int g = l >> 2, t = l & 3;
        int kb = ktf * 16 + 2 * t;
        int n0 = (2 * np) * 8 + g, n1 = n0 + 8;
        uint4 v;
        v.x = f2h2(W2[kb * 64 + n0],       W2[(kb + 1) * 64 + n0]);
        v.y = f2h2(W2[(kb + 8) * 64 + n0], W2[(kb + 9) * 64 + n0]);
        v.z = f2h2(W2[kb * 64 + n1],       W2[(kb + 1) * 64 + n1]);
        v.w = f2h2(W2[(kb + 8) * 64 + n1], W2[(kb + 9) * 64 + n1]);
        *(uint4*)(smem + OFF_W2F + (size_t)s * 16) = v;
    }
    if (tid < 64) {
        ((float*)(smem + OFF_B1))[tid] = b1[tid];
        ((float*)(smem + OFF_B2))[tid] = b2[tid];
    }
    if (tid == 0) {
        // batch dtype sniff: int64 payload (values < 2^31) has all-zero odd words
        int is64 = 1;
        for (int i = 1; i < 32; i += 2)
            if (bat[i] != 0) { is64 = 0; break; }
        *(int*)(smem + OFF_FLAG) = is64;
    }
    __syncthreads();
    const int is64 = *(const int*)(smem + OFF_FLAG);
    const float* b1s = (const float*)(smem + OFF_B1);
    const float* b2s = (const float*)(smem + OFF_B2);

    // ---- per-warp constants ----
    const int g = lane >> 2;                     // fragment row 0..7
    const int t = lane & 3;
    const uint32_t ringbase = sb + OFF_CMB + (uint32_t)w * (RING * CHUNK_B);
    char* obp = smem + OFF_OB + (size_t)w * 2048; // output bounce (16 rows x 128B)

    const int bid = blockIdx.x, grid = gridDim.x;
    const int numT = (NT - bid + grid - 1) / grid;
    const int total = numT * NCHUNK;

    float C[64];                                 // [m(2)][nt(8)][4]

    // batch indices for the first tile (consumed by its u-chunks c=6,7)
    int bt = load_bt(bid * DTILE + w * WROWS, E, lane, bat, is64);

    // prologue: PREF chunks ahead (c=0..3, no u-chunks -> bt not needed yet)
#pragma unroll
    for (int pc = 0; pc < PREF; pc++) {
        if (pc < total) {
            issue_chunk(ringbase + (uint32_t)pc * CHUNK_B,
                        bid * DTILE + w * WROWS, E, pc, lane, bt,
                        src, dst, ea, u);
        }
        cp_commit();   // commit even if empty to keep group count in sync
    }

    int slot_cons = 0;            // ring slot of chunk n
    int slot_iss  = PREF;         // ring slot of chunk n+PREF (PREF < RING)

    for (int n = 0; n < total; n++) {
        const int c = n & (NCHUNK - 1);
        const int tile = bid + (n >> 3) * grid;

        if (n + PREF < total) {
            int np_ = n + PREF;
            int cc = np_ & (NCHUNK - 1);
            int tl = bid + (np_ >> 3) * grid;
            if (cc == 0)          // new tile enters the pipeline: refresh bt early
                bt = load_bt(tl * DTILE + w * WROWS, E, lane, bat, is64);
            issue_chunk(ringbase + (uint32_t)slot_iss * CHUNK_B,
                        tl * DTILE + w * WROWS, E, cc, lane, bt,
                        src, dst, ea, u);
            cp_commit();
        }
        if (++slot_iss == RING) slot_iss = 0;
        cp_wait<PREF>();          // chunk n landed (PREF groups may remain)
        __syncwarp();

        if (c == 0) {
#pragma unroll
            for (int i = 0; i < 64; i++) C[i] = 0.f;
        }

        // ---------- layer-1 partial: 2 k16-groups of this chunk ----------
        const char* sbase = smem + OFF_CMB + (size_t)w * (RING * CHUNK_B)
                                 + (size_t)slot_cons * CHUNK_B;
        if (++slot_cons == RING) slot_cons = 0;
#pragma unroll
        for (int kl = 0; kl < 2; kl++) {
            const int ktf = c * 2 + kl;
            // A fragments: fp32 pairs from smem -> f16x2
            const uint32_t q0 = (uint32_t)(4 * kl + (t >> 1));
            const uint32_t off0 = (((q0 ^ (uint32_t)g) << 4) + (uint32_t)((t & 1) * 8));
            const uint32_t off2 = ((((q0 + 2) ^ (uint32_t)g) << 4) + (uint32_t)((t & 1) * 8));
            uint32_t a[2][4];
#pragma unroll
            for (int m = 0; m < 2; m++) {
                const char* rb = sbase + (m * 16 + g) * 128;
                float2 v;
                v = *(const float2*)(rb + off0);        a[m][0] = f2h2(v.x, v.y);
                v = *(const float2*)(rb + 1024 + off0); a[m][1] = f2h2(v.x, v.y);
                v = *(const float2*)(rb + off2);        a[m][2] = f2h2(v.x, v.y);
                v = *(const float2*)(rb + 1024 + off2); a[m][3] = f2h2(v.x, v.y);
            }
            const char* wf = smem + OFF_W1F + (size_t)ktf * 2048 + (size_t)lane * 16;
#pragma unroll
            for (int np = 0; np < 4; np++) {
                uint4 bv = *(const uint4*)(wf + np * 512);
#pragma unroll
                for (int m = 0; m < 2; m++) {
                    float* Cp = C + m * 32 + np * 8;
                    mmaf16(Cp,     a[m][0], a[m][1], a[m][2], a[m][3], bv.x, bv.y);
                    mmaf16(Cp + 4, a[m][0], a[m][1], a[m][2], a[m][3], bv.z, bv.w);
                }
            }
        }

        if (c != NCHUNK - 1) continue;

        // ---------- tail: per m-sub, h = relu(C+b1) -> f16 A regs (no smem) ----------
        const int tb = tile * DTILE + w * WROWS;
#pragma unroll
        for (int m = 0; m < 2; m++) {
            // C-fragment (c0,c1,c2,c3) == fp16 A-fragment pair layout: direct cvt
            uint32_t ah[16];
#pragma unroll
            for (int nt = 0; nt < 8; nt++) {
                float2 bb = *(const float2*)(b1s + nt * 8 + 2 * t);
                const float* Cm = C + m * 32 + nt * 4;
                ah[nt * 2]     = f2h2(fmaxf(Cm[0] + bb.x, 0.f), fmaxf(Cm[1] + bb.y, 0.f));
                ah[nt * 2 + 1] = f2h2(fmaxf(Cm[2] + bb.x, 0.f), fmaxf(Cm[3] + bb.y, 0.f));
            }

            // layer 2: C2[32] = h[16,64] @ W2  (A regs = ah quads)
            float C2[32];
#pragma unroll
            for (int i = 0; i < 32; i++) C2[i] = 0.f;
#pragma unroll
            for (int ktf = 0; ktf < 4; ktf++) {
                const char* wf = smem + OFF_W2F + (size_t)ktf * 2048 + (size_t)lane * 16;
#pragma unroll
                for (int np = 0; np < 4; np++) {
                    uint4 bv = *(const uint4*)(wf + np * 512);
                    mmaf16(C2 + np * 8,
                           ah[4 * ktf], ah[4 * ktf + 1], ah[4 * ktf + 2], ah[4 * ktf + 3],
                           bv.x, bv.y);
                    mmaf16(C2 + np * 8 + 4,
                           ah[4 * ktf], ah[4 * ktf + 1], ah[4 * ktf + 2], ah[4 * ktf + 3],
                           bv.z, bv.w);
                }
            }

            // ---- out = relu(C2 + b2): bounce through smem for coalesced STG.128 ----
            // bounce: 16 rows x 128B per n-half; quad swizzle q -> q ^ ((row&3)<<1)
#pragma unroll
            for (int nh = 0; nh < 2; nh++) {
#pragma unroll
                for (int j = 0; j < 4; j++) {
                    const int ntg = nh * 4 + j;
                    float2 bb = *(const float2*)(b2s + ntg * 8 + 2 * t);
                    const float* Cm = C2 + ntg * 4;
                    float2 v0 = make_float2(fmaxf(Cm[0] + bb.x, 0.f),
                                            fmaxf(Cm[1] + bb.y, 0.f));
                    float2 v1 = make_float2(fmaxf(Cm[2] + bb.x, 0.f),
                                            fmaxf(Cm[3] + bb.y, 0.f));
                    const int q = j * 2 + (t >> 1);
                    const int sq = (q ^ ((g & 3) << 1)) << 4;
                    const int ho = (t & 1) * 8;
                    *(float2*)(obp + g * 128 + sq + ho)       = v0;   // row g
                    *(float2*)(obp + (g + 8) * 128 + sq + ho) = v1;   // row g+8
                }
                __syncwarp();
#pragma unroll
                for (int j2 = 0; j2 < 4; j2++) {
                    const int rrow = j2 * 4 + (lane >> 3);            // 0..15
                    const int sq = ((lane & 7) ^ ((rrow & 3) << 1)) << 4;
                    uint4 v = *(const uint4*)(obp + rrow * 128 + sq);
                    const int e = tb + m * 16 + rrow;
                    if (e < E)
                        *(uint4*)(out + (size_t)e * 64 + nh * 32 + (lane & 7) * 4) = v;
                }
                __syncwarp();
            }
        }
    }
}

// ---------------- launch ----------------
extern "C" void kernel_launch(void* const* d_in, const int* in_sizes, int n_in,
                              void* d_out, int out_size) {
    const float* src = (const float*)d_in[0];
    const float* dst = (const float*)d_in[1];
    const float* ea  = (const float*)d_in[2];
    const float* u   = (const float*)d_in[3];
    const int*   bat = (const int*)d_in[4];   // int32 or int64 payload; sniffed in-kernel
    const float* W1  = (const float*)d_in[5];
    const float* b1  = (const float*)d_in[6];
    const float* W2  = (const float*)d_in[7];
    const float* b2  = (const float*)d_in[8];
    float* out = (float*)d_out;

    int E  = in_sizes[0] / 64;
    int NT = (E + DTILE - 1) / DTILE;

    int dev = 0;
    cudaGetDevice(&dev);
    int nsm = 148;
    cudaDeviceGetAttribute(&nsm, cudaDevAttrMultiProcessorCount, dev);
    int grid = (NT < nsm) ? NT : nsm;

    cudaFuncSetAttribute(megnet_edge_kernel,
                         cudaFuncAttributeMaxDynamicSharedMemorySize, SMEM_TOTAL);
    megnet_edge_kernel<<<grid, NTHR, SMEM_TOTAL>>>(src, dst, ea, u, bat,
                                                   W1, b1, W2, b2, out, E, NT);
    (void)n_in; (void)out_size;
}